// round 8
// baseline (speedup 1.0000x reference)
#include <cuda_runtime.h>
#include <cuda_fp16.h>
#include <cstdint>

// ============================================================================
// Problem constants
// ============================================================================
#define M_TOTAL 16384   // 8 * 2048
#define IN_F    4096    // K
#define OUT_F   4096    // N

// GEMM tiling — single-limb fp16 HMMA pipeline (legacy tensor path; tcgen05
// unusable: harness compiles through compute_103 base target which rejects
// tcgen05.ld/wait, so TMEM accumulators cannot be read back).
#define BM 128
#define BN 128
#define BK 64
#define STAGES 3
#define K_ITERS (IN_F / BK)               // 64

#define A_TILE_BYTES (BM * BK * 2)        // 16384
#define STAGE_BYTES  (2 * A_TILE_BYTES)   // A + B = 32768
#define SMEM_BYTES   (STAGES * STAGE_BYTES) // 98304 -> 2 CTAs/SM

// Fused prep kernel grid split
#define PREPW_BLOCKS 4096                         // one per W row
#define PREPX_THREADS 512
#define PREPX_F4_PER_THREAD 4
// total float4 in x = M_TOTAL*IN_F/4 = 16777216
#define PREPX_BLOCKS ((M_TOTAL * (size_t)IN_F / 4) / (PREPX_THREADS * PREPX_F4_PER_THREAD)) // 8192

// ============================================================================
// Scratch (device globals — no allocation allowed anywhere)
// ============================================================================
__device__ __half g_xh [(size_t)M_TOTAL * IN_F];   // 128 MB
__device__ __half g_sgn[(size_t)OUT_F * IN_F];     // 32 MB
__device__ float  g_scale[OUT_F];

// ============================================================================
// PTX helpers (sm_80 base-target instructions only)
// ============================================================================
__device__ __forceinline__ uint32_t smem_to_u32(const void* p) {
    uint32_t a;
    asm("{ .reg .u64 t; cvta.to.shared.u64 t, %1; cvt.u32.u64 %0, t; }"
        : "=r"(a) : "l"(p));
    return a;
}

__device__ __forceinline__ void cp_async16(uint32_t dst, const void* src) {
    asm volatile("cp.async.cg.shared.global [%0], [%1], 16;"
                 :: "r"(dst), "l"(src) : "memory");
}
#define CP_COMMIT()  asm volatile("cp.async.commit_group;" ::: "memory")
#define CP_WAIT(n)   asm volatile("cp.async.wait_group %0;" :: "n"(n) : "memory")

__device__ __forceinline__ void ldsm4(uint32_t* r, uint32_t addr) {
    asm volatile("ldmatrix.sync.aligned.m8n8.x4.shared.b16 {%0,%1,%2,%3}, [%4];"
                 : "=r"(r[0]), "=r"(r[1]), "=r"(r[2]), "=r"(r[3]) : "r"(addr));
}

__device__ __forceinline__ void mma16816(float* d, const uint32_t* a,
                                         uint32_t b0, uint32_t b1) {
    asm volatile(
        "mma.sync.aligned.m16n8k16.row.col.f32.f16.f16.f32 "
        "{%0,%1,%2,%3}, {%4,%5,%6,%7}, {%8,%9}, {%0,%1,%2,%3};"
        : "+f"(d[0]), "+f"(d[1]), "+f"(d[2]), "+f"(d[3])
        : "r"(a[0]), "r"(a[1]), "r"(a[2]), "r"(a[3]), "r"(b0), "r"(b1));
}

// ============================================================================
// Fused preprocess:
//   blocks [0, PREPW_BLOCKS):       W row -> sign (fp16, exact) + scale
//   blocks [PREPW_BLOCKS, +PREPX):  x fp32 -> fp16 streaming convert
// prep_w work (18us) hides under the x-convert memory stream.
// ============================================================================
__global__ void __launch_bounds__(PREPX_THREADS)
prep_fused_kernel(const float* __restrict__ x,
                  const float* __restrict__ w,
                  __half* __restrict__ sgn,
                  __half2* __restrict__ xh,
                  float* __restrict__ scale) {
    const int bid = blockIdx.x;
    const int tid = threadIdx.x;

    if (bid < PREPW_BLOCKS) {
        // ---- W row: sign + mean|w| (256 active threads) ----
        __shared__ float red[256];
        if (tid < 256) {
            const int o = bid;
            const float4* wr = reinterpret_cast<const float4*>(w + (size_t)o * IN_F);
            __half2* sr = reinterpret_cast<__half2*>(sgn + (size_t)o * IN_F);

            const __half P1 = __float2half(1.0f);
            const __half M1 = __float2half(-1.0f);
            const __half Z0 = __float2half(0.0f);

            float acc = 0.0f;
            for (int i = tid; i < IN_F / 4; i += 256) {
                float4 v = wr[i];
                acc += fabsf(v.x) + fabsf(v.y) + fabsf(v.z) + fabsf(v.w);
                __half s0 = (v.x > 0.f) ? P1 : ((v.x < 0.f) ? M1 : Z0);
                __half s1 = (v.y > 0.f) ? P1 : ((v.y < 0.f) ? M1 : Z0);
                __half s2 = (v.z > 0.f) ? P1 : ((v.z < 0.f) ? M1 : Z0);
                __half s3 = (v.w > 0.f) ? P1 : ((v.w < 0.f) ? M1 : Z0);
                sr[2 * i]     = __halves2half2(s0, s1);
                sr[2 * i + 1] = __halves2half2(s2, s3);
            }
            red[tid] = acc;
        }
        __syncthreads();
        if (tid < 256) {
            #pragma unroll
            for (int off = 128; off > 0; off >>= 1) {
                if (tid < off) red[tid] += red[tid + off];
                __syncthreads();
            }
            if (tid == 0) scale[bid] = red[0] * (1.0f / (float)IN_F);
        }
    } else {
        // ---- x convert: 4 independent float4 per thread (MLP=4) ----
        const size_t xb = (size_t)(bid - PREPW_BLOCKS);
        const size_t base = (xb * PREPX_THREADS + tid) * PREPX_F4_PER_THREAD;
        const float4* xr = reinterpret_cast<const float4*>(x);
        float4 v[PREPX_F4_PER_THREAD];
        #pragma unroll
        for (int i = 0; i < PREPX_F4_PER_THREAD; i++) v[i] = xr[base + i];
        #pragma unroll
        for (int i = 0; i < PREPX_F4_PER_THREAD; i++) {
            xh[2 * (base + i)]     = __halves2half2(__float2half(v[i].x),
                                                    __float2half(v[i].y));
            xh[2 * (base + i) + 1] = __halves2half2(__float2half(v[i].z),
                                                    __float2half(v[i].w));
        }
    }
}

// ============================================================================
// Main GEMM: out[m,n] = scale[n] * sum_k xh[m,k]*sgn[n,k] + bias[n]
//   cp.async 3-stage pipeline, SW128 XOR-swizzled smem, ldmatrix + HMMA 16816.
//   8 warps: 4(M) x 2(N); warp tile 32x64. 2 CTAs/SM for issue coverage.
//   (Unchanged from R7 — measured at ~the legacy HMMA issue floor.)
// ============================================================================
__global__ void __launch_bounds__(256, 2)
hgemm_kernel(const float* __restrict__ bias, float* __restrict__ out) {
    extern __shared__ __align__(1024) char smem[];
    const uint32_t sb = smem_to_u32(smem);

    const int tid  = threadIdx.x;
    const int lane = tid & 31;
    const int warp = tid >> 5;
    const int wm = warp & 3;          // 0..3  (M strips of 32)
    const int wn = warp >> 2;         // 0..1  (N strips of 64)

    const int m0 = blockIdx.y * BM;
    const int n0 = blockIdx.x * BN;

    // ---- gmem source rows for cp.async (each thread: one 16B chunk, 4 rows)
    const int lrow = tid >> 3;        // 0..31
    const int lch  = tid & 7;         // 0..7 (16B chunk within 128B row)
    const __half* Ap = g_xh  + (size_t)m0 * IN_F;
    const __half* Bp = g_sgn + (size_t)n0 * IN_F;

    // ---- ldmatrix per-thread address components (SW128: chunk ^= row&7)
    const int rA    = lane & 15;          // A row within m16 tile
    const int halfA = lane >> 4;          // which 16B k-chunk
    const uint32_t aRowOff = (uint32_t)(wm * 32 + rA) * 128;
    const int swA = rA & 7;

    const int grp = lane >> 3;
    const int l8  = lane & 7;
    const int rB  = wn * 64 + ((grp >> 1) << 3) + l8;  // B (n) row
    const int halfB = grp & 1;
    const uint32_t bRowOff = (uint32_t)rB * 128;
    const int swB = rB & 7;

    float acc[2][8][4];
    #pragma unroll
    for (int t = 0; t < 2; t++)
        #pragma unroll
        for (int j = 0; j < 8; j++)
            #pragma unroll
            for (int r = 0; r < 4; r++) acc[t][j][r] = 0.0f;

    // ---- stage loader -------------------------------------------------------
    auto load_stage = [&](int s, int ki) {
        const int k0 = ki * BK;
        const uint32_t so = sb + (uint32_t)s * STAGE_BYTES;
        #pragma unroll
        for (int r = 0; r < 4; r++) {
            const int row = lrow + 32 * r;
            const size_t go = (size_t)row * IN_F + k0 + lch * 8;
            const uint32_t sw = (uint32_t)row * 128 +
                                (uint32_t)((lch ^ (row & 7)) << 4);
            cp_async16(so + sw,                Ap + go);
            cp_async16(so + A_TILE_BYTES + sw, Bp + go);
        }
    };

    // ---- prologue: fill STAGES-1 stages ----
    #pragma unroll
    for (int s = 0; s < STAGES - 1; s++) {
        load_stage(s, s);
        CP_COMMIT();
    }

    // ---- mainloop ----
    for (int i = 0; i < K_ITERS; i++) {
        CP_WAIT(STAGES - 2);      // stage i's group complete
        __syncthreads();          // all warps done with the stage being refilled

        const int nld = i + STAGES - 1;
        if (nld < K_ITERS) load_stage(nld % STAGES, nld);
        CP_COMMIT();

        const uint32_t so = sb + (uint32_t)(i % STAGES) * STAGE_BYTES;
        const uint32_t aA = so;
        const uint32_t bB = so + A_TILE_BYTES;

        #pragma unroll
        for (int kk = 0; kk < 4; kk++) {
            const int c = kk * 2;

            // B fragments: 4 x ldmatrix.x4 -> 8 n8-tiles of k16
            uint32_t bf[4][4];
            #pragma unroll
            for (int j = 0; j < 4; j++) {
                uint32_t addr = bB + bRowOff + (uint32_t)j * 2048 +
                                (uint32_t)(((c + halfB) ^ swB) << 4);
                ldsm4(bf[j], addr);
            }

            // A fragments: 2 m16-tiles of k16
            uint32_t af[2][4];
            {
                uint32_t sw16 = (uint32_t)(((c + halfA) ^ swA) << 4);
                ldsm4(af[0], aA + aRowOff + sw16);
                ldsm4(af[1], aA + aRowOff + 2048 + sw16);
            }

            // 16 HMMAs
            #pragma unroll
            for (int t = 0; t < 2; t++)
                #pragma unroll
                for (int j = 0; j < 4; j++) {
                    mma16816(acc[t][2 * j],     af[t], bf[j][0], bf[j][1]);
                    mma16816(acc[t][2 * j + 1], af[t], bf[j][2], bf[j][3]);
                }
        }
    }

    // ---- epilogue: y = scale[n]*acc + bias[n], float2 stores ----
    const int gm  = m0 + wm * 32 + (lane >> 2);
    const int gn0 = n0 + wn * 64 + (lane & 3) * 2;
    #pragma unroll
    for (int t = 0; t < 2; t++) {
        const int r0 = gm + t * 16;
        #pragma unroll
        for (int j = 0; j < 8; j++) {
            const int n = gn0 + j * 8;
            const float2 sc = *reinterpret_cast<const float2*>(g_scale + n);
            const float2 bi = *reinterpret_cast<const float2*>(bias + n);
            float2 v0, v1;
            v0.x = acc[t][j][0] * sc.x + bi.x;
            v0.y = acc[t][j][1] * sc.y + bi.y;
            v1.x = acc[t][j][2] * sc.x + bi.x;
            v1.y = acc[t][j][3] * sc.y + bi.y;
            *reinterpret_cast<float2*>(out + (size_t)r0 * OUT_F + n)       = v0;
            *reinterpret_cast<float2*>(out + (size_t)(r0 + 8) * OUT_F + n) = v1;
        }
    }
}

// ============================================================================
// Host side
// ============================================================================
extern "C" void kernel_launch(void* const* d_in, const int* in_sizes, int n_in,
                              void* d_out, int out_size) {
    const float* x    = (const float*)d_in[0];
    const float* w    = (const float*)d_in[1];
    const float* bias = (const float*)d_in[2];
    float* out = (float*)d_out;

    void *pxh = nullptr, *psgn = nullptr, *pscale = nullptr;
    cudaGetSymbolAddress(&pxh, g_xh);
    cudaGetSymbolAddress(&psgn, g_sgn);
    cudaGetSymbolAddress(&pscale, g_scale);

    // Fused preprocess: W-sign/scale blocks + x-convert blocks in one launch
    {
        unsigned grid = (unsigned)(PREPW_BLOCKS + PREPX_BLOCKS);  // 4096 + 8192
        prep_fused_kernel<<<grid, PREPX_THREADS>>>(
            x, w, (__half*)psgn, (__half2*)pxh, (float*)pscale);
    }

    // Main GEMM
    cudaFuncSetAttribute(hgemm_kernel,
                         cudaFuncAttributeMaxDynamicSharedMemorySize, SMEM_BYTES);

    dim3 grid(OUT_F / BN, M_TOTAL / BM);   // (32, 128)
    hgemm_kernel<<<grid, 256, SMEM_BYTES>>>(bias, out);
}

// round 9
// speedup vs baseline: 1.0130x; 1.0130x over previous
#include <cuda_runtime.h>
#include <cuda_fp16.h>
#include <cstdint>

// ============================================================================
// Problem constants
// ============================================================================
#define M_TOTAL 16384   // 8 * 2048
#define IN_F    4096    // K
#define OUT_F   4096    // N

// GEMM tiling — single-limb fp16 HMMA pipeline (legacy tensor path; tcgen05
// unusable: harness compiles through compute_103 base target which rejects
// tcgen05.ld/wait, so TMEM accumulators cannot be read back).
#define BM 128
#define BN 128
#define BK 64
#define STAGES 3
#define K_ITERS (IN_F / BK)               // 64

#define A_TILE_BYTES (BM * BK * 2)        // 16384
#define STAGE_BYTES  (2 * A_TILE_BYTES)   // A + B = 32768
#define SMEM_BYTES   (STAGES * STAGE_BYTES) // 98304 -> 2 CTAs/SM

// ============================================================================
// Scratch (device globals — no allocation allowed anywhere)
// ============================================================================
__device__ __half g_xh [(size_t)M_TOTAL * IN_F];   // 128 MB
__device__ __half g_sgn[(size_t)OUT_F * IN_F];     // 32 MB
__device__ float  g_scale[OUT_F];

// ============================================================================
// PTX helpers (sm_80 base-target instructions only)
// ============================================================================
__device__ __forceinline__ uint32_t smem_to_u32(const void* p) {
    uint32_t a;
    asm("{ .reg .u64 t; cvta.to.shared.u64 t, %1; cvt.u32.u64 %0, t; }"
        : "=r"(a) : "l"(p));
    return a;
}

__device__ __forceinline__ void cp_async16(uint32_t dst, const void* src) {
    asm volatile("cp.async.cg.shared.global [%0], [%1], 16;"
                 :: "r"(dst), "l"(src) : "memory");
}
#define CP_COMMIT()  asm volatile("cp.async.commit_group;" ::: "memory")
#define CP_WAIT(n)   asm volatile("cp.async.wait_group %0;" :: "n"(n) : "memory")

__device__ __forceinline__ void ldsm4(uint32_t* r, uint32_t addr) {
    asm volatile("ldmatrix.sync.aligned.m8n8.x4.shared.b16 {%0,%1,%2,%3}, [%4];"
                 : "=r"(r[0]), "=r"(r[1]), "=r"(r[2]), "=r"(r[3]) : "r"(addr));
}

__device__ __forceinline__ void mma16816(float* d, const uint32_t* a,
                                         uint32_t b0, uint32_t b1) {
    asm volatile(
        "mma.sync.aligned.m16n8k16.row.col.f32.f16.f16.f32 "
        "{%0,%1,%2,%3}, {%4,%5,%6,%7}, {%8,%9}, {%0,%1,%2,%3};"
        : "+f"(d[0]), "+f"(d[1]), "+f"(d[2]), "+f"(d[3])
        : "r"(a[0]), "r"(a[1]), "r"(a[2]), "r"(a[3]), "r"(b0), "r"(b1));
}

// ============================================================================
// Preprocess: W -> sign (fp16 +-1/0, exact) + per-row scale (mean |w|, fp32)
// (separate launches — R8's fused variant regressed; reverted)
// ============================================================================
__global__ void __launch_bounds__(256)
prep_w_kernel(const float* __restrict__ w,
              __half* __restrict__ sgn,
              float* __restrict__ scale) {
    const int o = blockIdx.x;
    const int tid = threadIdx.x;
    const float4* wr = reinterpret_cast<const float4*>(w + (size_t)o * IN_F);
    __half2* sr = reinterpret_cast<__half2*>(sgn + (size_t)o * IN_F);

    const __half P1 = __float2half(1.0f);
    const __half M1 = __float2half(-1.0f);
    const __half Z0 = __float2half(0.0f);

    float acc = 0.0f;
    for (int i = tid; i < IN_F / 4; i += 256) {
        float4 v = wr[i];
        acc += fabsf(v.x) + fabsf(v.y) + fabsf(v.z) + fabsf(v.w);
        __half s0 = (v.x > 0.f) ? P1 : ((v.x < 0.f) ? M1 : Z0);
        __half s1 = (v.y > 0.f) ? P1 : ((v.y < 0.f) ? M1 : Z0);
        __half s2 = (v.z > 0.f) ? P1 : ((v.z < 0.f) ? M1 : Z0);
        __half s3 = (v.w > 0.f) ? P1 : ((v.w < 0.f) ? M1 : Z0);
        sr[2 * i]     = __halves2half2(s0, s1);
        sr[2 * i + 1] = __halves2half2(s2, s3);
    }

    __shared__ float red[256];
    red[tid] = acc;
    __syncthreads();
    #pragma unroll
    for (int off = 128; off > 0; off >>= 1) {
        if (tid < off) red[tid] += red[tid + off];
        __syncthreads();
    }
    if (tid == 0) scale[o] = red[0] * (1.0f / (float)IN_F);
}

__global__ void __launch_bounds__(256)
prep_x_kernel(const float4* __restrict__ x, __half2* __restrict__ xh) {
    size_t idx = (size_t)blockIdx.x * 256 + threadIdx.x;
    float4 v = x[idx];
    xh[2 * idx]     = __halves2half2(__float2half(v.x), __float2half(v.y));
    xh[2 * idx + 1] = __halves2half2(__float2half(v.z), __float2half(v.w));
}

// ============================================================================
// Main GEMM: out[m,n] = scale[n] * sum_k xh[m,k]*sgn[n,k] + bias[n]
//   cp.async 3-stage pipeline, SW128 XOR-swizzled smem, ldmatrix + HMMA 16816.
//   8 warps: 4(M) x 2(N); warp tile 32x64; 2 CTAs/SM.
//   NEW (R9): register double-buffered fragments — chunk kk+1's LDSMs issue
//   before chunk kk's 16 HMMAs, hiding the ~30cyc LDSM->HMMA RAW stall.
// ============================================================================
__global__ void __launch_bounds__(256, 2)
hgemm_kernel(const float* __restrict__ bias, float* __restrict__ out) {
    extern __shared__ __align__(1024) char smem[];
    const uint32_t sb = smem_to_u32(smem);

    const int tid  = threadIdx.x;
    const int lane = tid & 31;
    const int warp = tid >> 5;
    const int wm = warp & 3;          // 0..3  (M strips of 32)
    const int wn = warp >> 2;         // 0..1  (N strips of 64)

    const int m0 = blockIdx.y * BM;
    const int n0 = blockIdx.x * BN;

    // ---- gmem source rows for cp.async (each thread: one 16B chunk, 4 rows)
    const int lrow = tid >> 3;        // 0..31
    const int lch  = tid & 7;         // 0..7 (16B chunk within 128B row)
    const __half* Ap = g_xh  + (size_t)m0 * IN_F;
    const __half* Bp = g_sgn + (size_t)n0 * IN_F;

    // ---- ldmatrix per-thread address components (SW128: chunk ^= row&7)
    const int rA    = lane & 15;          // A row within m16 tile
    const int halfA = lane >> 4;          // which 16B k-chunk
    const uint32_t aRowOff = (uint32_t)(wm * 32 + rA) * 128;
    const int swA = rA & 7;

    const int grp = lane >> 3;
    const int l8  = lane & 7;
    const int rB  = wn * 64 + ((grp >> 1) << 3) + l8;  // B (n) row
    const int halfB = grp & 1;
    const uint32_t bRowOff = (uint32_t)rB * 128;
    const int swB = rB & 7;

    float acc[2][8][4];
    #pragma unroll
    for (int t = 0; t < 2; t++)
        #pragma unroll
        for (int j = 0; j < 8; j++)
            #pragma unroll
            for (int r = 0; r < 4; r++) acc[t][j][r] = 0.0f;

    // ---- stage loader -------------------------------------------------------
    auto load_stage = [&](int s, int ki) {
        const int k0 = ki * BK;
        const uint32_t so = sb + (uint32_t)s * STAGE_BYTES;
        #pragma unroll
        for (int r = 0; r < 4; r++) {
            const int row = lrow + 32 * r;
            const size_t go = (size_t)row * IN_F + k0 + lch * 8;
            const uint32_t sw = (uint32_t)row * 128 +
                                (uint32_t)((lch ^ (row & 7)) << 4);
            cp_async16(so + sw,                Ap + go);
            cp_async16(so + A_TILE_BYTES + sw, Bp + go);
        }
    };

    // ---- fragment loader (one k16 chunk c = 0,2,4,6 within the stage) ------
    uint32_t af[2][2][4];     // [buf][m16 tile][regs]
    uint32_t bf[2][4][4];     // [buf][n16 tile][regs]
    auto load_frags = [&](int buf, uint32_t aA, uint32_t bB, int c) {
        #pragma unroll
        for (int j = 0; j < 4; j++) {
            uint32_t addr = bB + bRowOff + (uint32_t)j * 2048 +
                            (uint32_t)(((c + halfB) ^ swB) << 4);
            ldsm4(bf[buf][j], addr);
        }
        uint32_t sw16 = (uint32_t)(((c + halfA) ^ swA) << 4);
        ldsm4(af[buf][0], aA + aRowOff + sw16);
        ldsm4(af[buf][1], aA + aRowOff + 2048 + sw16);
    };

    // ---- prologue: fill STAGES-1 stages ----
    #pragma unroll
    for (int s = 0; s < STAGES - 1; s++) {
        load_stage(s, s);
        CP_COMMIT();
    }

    // ---- mainloop ----
    for (int i = 0; i < K_ITERS; i++) {
        CP_WAIT(STAGES - 2);      // stage i's group complete
        __syncthreads();          // all warps done with the stage being refilled

        const int nld = i + STAGES - 1;
        if (nld < K_ITERS) load_stage(nld % STAGES, nld);
        CP_COMMIT();

        const uint32_t so = sb + (uint32_t)(i % STAGES) * STAGE_BYTES;
        const uint32_t aA = so;
        const uint32_t bB = so + A_TILE_BYTES;

        load_frags(0, aA, bB, 0);   // prime chunk 0

        #pragma unroll
        for (int kk = 0; kk < 4; kk++) {
            const int cur = kk & 1;
            if (kk < 3) load_frags(cur ^ 1, aA, bB, (kk + 1) * 2);

            // 16 HMMAs on the current buffer
            #pragma unroll
            for (int t = 0; t < 2; t++)
                #pragma unroll
                for (int j = 0; j < 4; j++) {
                    mma16816(acc[t][2 * j],     af[cur][t], bf[cur][j][0], bf[cur][j][1]);
                    mma16816(acc[t][2 * j + 1], af[cur][t], bf[cur][j][2], bf[cur][j][3]);
                }
        }
    }

    // ---- epilogue: y = scale[n]*acc + bias[n], float2 stores ----
    const int gm  = m0 + wm * 32 + (lane >> 2);
    const int gn0 = n0 + wn * 64 + (lane & 3) * 2;
    #pragma unroll
    for (int t = 0; t < 2; t++) {
        const int r0 = gm + t * 16;
        #pragma unroll
        for (int j = 0; j < 8; j++) {
            const int n = gn0 + j * 8;
            const float2 sc = *reinterpret_cast<const float2*>(g_scale + n);
            const float2 bi = *reinterpret_cast<const float2*>(bias + n);
            float2 v0, v1;
            v0.x = acc[t][j][0] * sc.x + bi.x;
            v0.y = acc[t][j][1] * sc.y + bi.y;
            v1.x = acc[t][j][2] * sc.x + bi.x;
            v1.y = acc[t][j][3] * sc.y + bi.y;
            *reinterpret_cast<float2*>(out + (size_t)r0 * OUT_F + n)       = v0;
            *reinterpret_cast<float2*>(out + (size_t)(r0 + 8) * OUT_F + n) = v1;
        }
    }
}

// ============================================================================
// Host side
// ============================================================================
extern "C" void kernel_launch(void* const* d_in, const int* in_sizes, int n_in,
                              void* d_out, int out_size) {
    const float* x    = (const float*)d_in[0];
    const float* w    = (const float*)d_in[1];
    const float* bias = (const float*)d_in[2];
    float* out = (float*)d_out;

    void *pxh = nullptr, *psgn = nullptr, *pscale = nullptr;
    cudaGetSymbolAddress(&pxh, g_xh);
    cudaGetSymbolAddress(&psgn, g_sgn);
    cudaGetSymbolAddress(&pscale, g_scale);

    // Preprocess (separate launches — fused variant measured slower)
    prep_w_kernel<<<OUT_F, 256>>>(w, (__half*)psgn, (float*)pscale);
    {
        size_t n4 = ((size_t)M_TOTAL * IN_F) / 4;
        prep_x_kernel<<<(unsigned)(n4 / 256), 256>>>(
            (const float4*)x, (__half2*)pxh);
    }

    // Main GEMM
    cudaFuncSetAttribute(hgemm_kernel,
                         cudaFuncAttributeMaxDynamicSharedMemorySize, SMEM_BYTES);

    dim3 grid(OUT_F / BN, M_TOTAL / BM);   // (32, 128)
    hgemm_kernel<<<grid, 256, SMEM_BYTES>>>(bias, out);
}

// round 10
// speedup vs baseline: 1.1838x; 1.1686x over previous
#include <cuda_runtime.h>
#include <cuda_fp16.h>
#include <cstdint>

// ============================================================================
// Problem constants
// ============================================================================
#define M_TOTAL 16384   // 8 * 2048
#define IN_F    4096    // K
#define OUT_F   4096    // N

// GEMM tiling — single-limb fp16 HMMA pipeline (legacy tensor path; tcgen05
// unusable: harness compiles through compute_103 base target which rejects
// tcgen05.ld/wait, so TMEM accumulators cannot be read back).
#define BM 128
#define BN 128
#define BK 64
#define STAGES 3
#define K_ITERS (IN_F / BK)               // 64

#define A_TILE_BYTES (BM * BK * 2)        // 16384
#define STAGE_BYTES  (2 * A_TILE_BYTES)   // A + B = 32768
#define SMEM_TILE0   1024                 // tiles start here (1KB-aligned swizzle)
#define SMEM_BYTES   (SMEM_TILE0 + STAGES * STAGE_BYTES)  // 99328 -> 2 CTAs/SM

// mbarrier offsets (in the first 1KB)
#define OFF_FULL(s)  ((s) * 16)
#define OFF_EMPTY(s) ((s) * 16 + 8)

// ============================================================================
// Scratch (device globals — no allocation allowed anywhere)
// ============================================================================
__device__ __half g_xh [(size_t)M_TOTAL * IN_F];   // 128 MB
__device__ __half g_sgn[(size_t)OUT_F * IN_F];     // 32 MB
__device__ float  g_scale[OUT_F];

// ============================================================================
// PTX helpers (sm_80 base-target instructions only)
// ============================================================================
__device__ __forceinline__ uint32_t smem_to_u32(const void* p) {
    uint32_t a;
    asm("{ .reg .u64 t; cvta.to.shared.u64 t, %1; cvt.u32.u64 %0, t; }"
        : "=r"(a) : "l"(p));
    return a;
}

__device__ __forceinline__ void cp_async16(uint32_t dst, const void* src) {
    asm volatile("cp.async.cg.shared.global [%0], [%1], 16;"
                 :: "r"(dst), "l"(src) : "memory");
}

// cp.async completion -> mbarrier arrive (sm_80+; .noinc: count pre-set at init)
#define CP_ASYNC_MBAR_ARRIVE(mbar) \
    asm volatile("cp.async.mbarrier.arrive.noinc.shared.b64 [%0];" \
                 :: "r"((uint32_t)(mbar)) : "memory")

#define MBARRIER_INIT(addr, cnt) \
    asm volatile("mbarrier.init.shared.b64 [%0], %1;" \
                 :: "r"((uint32_t)(addr)), "r"((uint32_t)(cnt)) : "memory")

#define MBARRIER_ARRIVE(addr) \
    asm volatile("mbarrier.arrive.shared.b64 _, [%0];" \
                 :: "r"((uint32_t)(addr)) : "memory")

#define MBARRIER_WAIT_PARITY(addr, parity) do {                               \
    uint32_t _mb = (uint32_t)(addr);                                          \
    uint32_t _ph = (uint32_t)(parity);                                        \
    asm volatile(                                                             \
        "{\n\t.reg .pred P1;\n\t"                                             \
        "WAIT_LOOP_%=:\n\t"                                                   \
        "mbarrier.try_wait.parity.shared.b64 P1, [%0], %1;\n\t"               \
        "@P1 bra.uni WAIT_DONE_%=;\n\t"                                       \
        "bra.uni WAIT_LOOP_%=;\n\t"                                           \
        "WAIT_DONE_%=:\n\t}"                                                  \
        :: "r"(_mb), "r"(_ph) : "memory");                                    \
} while (0)

__device__ __forceinline__ void ldsm4(uint32_t* r, uint32_t addr) {
    asm volatile("ldmatrix.sync.aligned.m8n8.x4.shared.b16 {%0,%1,%2,%3}, [%4];"
                 : "=r"(r[0]), "=r"(r[1]), "=r"(r[2]), "=r"(r[3]) : "r"(addr));
}

__device__ __forceinline__ void mma16816(float* d, const uint32_t* a,
                                         uint32_t b0, uint32_t b1) {
    asm volatile(
        "mma.sync.aligned.m16n8k16.row.col.f32.f16.f16.f32 "
        "{%0,%1,%2,%3}, {%4,%5,%6,%7}, {%8,%9}, {%0,%1,%2,%3};"
        : "+f"(d[0]), "+f"(d[1]), "+f"(d[2]), "+f"(d[3])
        : "r"(a[0]), "r"(a[1]), "r"(a[2]), "r"(a[3]), "r"(b0), "r"(b1));
}

// ============================================================================
// Preprocess: W -> sign (fp16 +-1/0, exact) + per-row scale (mean |w|, fp32)
// ============================================================================
__global__ void __launch_bounds__(256)
prep_w_kernel(const float* __restrict__ w,
              __half* __restrict__ sgn,
              float* __restrict__ scale) {
    const int o = blockIdx.x;
    const int tid = threadIdx.x;
    const float4* wr = reinterpret_cast<const float4*>(w + (size_t)o * IN_F);
    __half2* sr = reinterpret_cast<__half2*>(sgn + (size_t)o * IN_F);

    const __half P1 = __float2half(1.0f);
    const __half M1 = __float2half(-1.0f);
    const __half Z0 = __float2half(0.0f);

    float acc = 0.0f;
    for (int i = tid; i < IN_F / 4; i += 256) {
        float4 v = wr[i];
        acc += fabsf(v.x) + fabsf(v.y) + fabsf(v.z) + fabsf(v.w);
        __half s0 = (v.x > 0.f) ? P1 : ((v.x < 0.f) ? M1 : Z0);
        __half s1 = (v.y > 0.f) ? P1 : ((v.y < 0.f) ? M1 : Z0);
        __half s2 = (v.z > 0.f) ? P1 : ((v.z < 0.f) ? M1 : Z0);
        __half s3 = (v.w > 0.f) ? P1 : ((v.w < 0.f) ? M1 : Z0);
        sr[2 * i]     = __halves2half2(s0, s1);
        sr[2 * i + 1] = __halves2half2(s2, s3);
    }

    __shared__ float red[256];
    red[tid] = acc;
    __syncthreads();
    #pragma unroll
    for (int off = 128; off > 0; off >>= 1) {
        if (tid < off) red[tid] += red[tid + off];
        __syncthreads();
    }
    if (tid == 0) scale[o] = red[0] * (1.0f / (float)IN_F);
}

__global__ void __launch_bounds__(256)
prep_x_kernel(const float4* __restrict__ x, __half2* __restrict__ xh) {
    size_t idx = (size_t)blockIdx.x * 256 + threadIdx.x;
    float4 v = x[idx];
    xh[2 * idx]     = __halves2half2(__float2half(v.x), __float2half(v.y));
    xh[2 * idx + 1] = __halves2half2(__float2half(v.z), __float2half(v.w));
}

// ============================================================================
// Main GEMM: out[m,n] = scale[n] * sum_k xh[m,k]*sgn[n,k] + bias[n]
//   R10: mbarrier full/empty pipeline replaces CP_WAIT+__syncthreads —
//   warps free-run with skew, LDSM bursts decorrelate, tensor pipe stays fed.
//   full[s] count=256 (cp.async.mbarrier.arrive.noinc per thread)
//   empty[s] count=8  (one arrive per warp after last LDSM of the stage)
//   Fragments single-buffered (R9 showed double-buffering spills at 128 regs).
// ============================================================================
__global__ void __launch_bounds__(256, 2)
hgemm_kernel(const float* __restrict__ bias, float* __restrict__ out) {
    extern __shared__ __align__(1024) char smem[];
    const uint32_t sb = smem_to_u32(smem);

    const int tid  = threadIdx.x;
    const int lane = tid & 31;
    const int warp = tid >> 5;
    const int wm = warp & 3;          // 0..3  (M strips of 32)
    const int wn = warp >> 2;         // 0..1  (N strips of 64)

    const int m0 = blockIdx.y * BM;
    const int n0 = blockIdx.x * BN;

    // ---- gmem source rows for cp.async (each thread: one 16B chunk, 4 rows)
    const int lrow = tid >> 3;        // 0..31
    const int lch  = tid & 7;         // 0..7 (16B chunk within 128B row)
    const __half* Ap = g_xh  + (size_t)m0 * IN_F;
    const __half* Bp = g_sgn + (size_t)n0 * IN_F;

    // ---- ldmatrix per-thread address components (SW128: chunk ^= row&7)
    const int rA    = lane & 15;          // A row within m16 tile
    const int halfA = lane >> 4;          // which 16B k-chunk
    const uint32_t aRowOff = (uint32_t)(wm * 32 + rA) * 128;
    const int swA = rA & 7;

    const int grp = lane >> 3;
    const int l8  = lane & 7;
    const int rB  = wn * 64 + ((grp >> 1) << 3) + l8;  // B (n) row
    const int halfB = grp & 1;
    const uint32_t bRowOff = (uint32_t)rB * 128;
    const int swB = rB & 7;

    // ---- mbarrier init ----
    if (tid == 0) {
        #pragma unroll
        for (int s = 0; s < STAGES; s++) {
            MBARRIER_INIT(sb + OFF_FULL(s), 256);
            MBARRIER_INIT(sb + OFF_EMPTY(s), 8);
        }
    }
    __syncthreads();

    float acc[2][8][4];
    #pragma unroll
    for (int t = 0; t < 2; t++)
        #pragma unroll
        for (int j = 0; j < 8; j++)
            #pragma unroll
            for (int r = 0; r < 4; r++) acc[t][j][r] = 0.0f;

    // ---- stage loader: issue this thread's 8 cp.asyncs for k-iter ki ----
    auto load_stage = [&](int s, int ki) {
        const int k0 = ki * BK;
        const uint32_t so = sb + SMEM_TILE0 + (uint32_t)s * STAGE_BYTES;
        #pragma unroll
        for (int r = 0; r < 4; r++) {
            const int row = lrow + 32 * r;
            const size_t go = (size_t)row * IN_F + k0 + lch * 8;
            const uint32_t sw = (uint32_t)row * 128 +
                                (uint32_t)((lch ^ (row & 7)) << 4);
            cp_async16(so + sw,                Ap + go);
            cp_async16(so + A_TILE_BYTES + sw, Bp + go);
        }
    };

    // ---- fragment load + 16 HMMAs for one k16 chunk c in stage at (aA,bB) --
    auto do_chunk = [&](uint32_t aA, uint32_t bB, int c) {
        uint32_t bf[4][4];
        #pragma unroll
        for (int j = 0; j < 4; j++) {
            uint32_t addr = bB + bRowOff + (uint32_t)j * 2048 +
                            (uint32_t)(((c + halfB) ^ swB) << 4);
            ldsm4(bf[j], addr);
        }
        uint32_t af[2][4];
        {
            uint32_t sw16 = (uint32_t)(((c + halfA) ^ swA) << 4);
            ldsm4(af[0], aA + aRowOff + sw16);
            ldsm4(af[1], aA + aRowOff + 2048 + sw16);
        }
        #pragma unroll
        for (int t = 0; t < 2; t++)
            #pragma unroll
            for (int j = 0; j < 4; j++) {
                mma16816(acc[t][2 * j],     af[t], bf[j][0], bf[j][1]);
                mma16816(acc[t][2 * j + 1], af[t], bf[j][2], bf[j][3]);
            }
    };

    // ---- prologue: fill all 3 stages, arrival tracked per thread ----
    #pragma unroll
    for (int s = 0; s < STAGES; s++) {
        load_stage(s, s);
        CP_ASYNC_MBAR_ARRIVE(sb + OFF_FULL(s));
    }

    // ---- mainloop: consumer cursor (st_c, ph_c), producer cursor (st_p, ph_p)
    int st_c = 0, ph_c = 0;
    int st_p = 0, ph_p = 0;   // produce at iter i targets slot (i+2)%3; its
                              // empty completes after consumption at iter i-1
    for (int i = 0; i < K_ITERS; i++) {
        MBARRIER_WAIT_PARITY(sb + OFF_FULL(st_c), ph_c);

        const uint32_t so = sb + SMEM_TILE0 + (uint32_t)st_c * STAGE_BYTES;
        const uint32_t aA = so;
        const uint32_t bB = so + A_TILE_BYTES;

        do_chunk(aA, bB, 0);

        // produce stage i+2 (slots 3..K_ITERS-1 filled here; 0..2 in prologue)
        if (i >= 1 && i <= K_ITERS - 3) {
            MBARRIER_WAIT_PARITY(sb + OFF_EMPTY(st_p), ph_p);
            load_stage(st_p, i + 2);
            CP_ASYNC_MBAR_ARRIVE(sb + OFF_FULL(st_p));
            if (++st_p == STAGES) { st_p = 0; ph_p ^= 1; }
        }

        do_chunk(aA, bB, 2);
        do_chunk(aA, bB, 4);
        do_chunk(aA, bB, 6);

        // this warp is done reading stage st_c
        if (lane == 0) MBARRIER_ARRIVE(sb + OFF_EMPTY(st_c));
        if (++st_c == STAGES) { st_c = 0; ph_c ^= 1; }
    }

    // ---- epilogue: y = scale[n]*acc + bias[n], float2 stores ----
    const int gm  = m0 + wm * 32 + (lane >> 2);
    const int gn0 = n0 + wn * 64 + (lane & 3) * 2;
    #pragma unroll
    for (int t = 0; t < 2; t++) {
        const int r0 = gm + t * 16;
        #pragma unroll
        for (int j = 0; j < 8; j++) {
            const int n = gn0 + j * 8;
            const float2 sc = *reinterpret_cast<const float2*>(g_scale + n);
            const float2 bi = *reinterpret_cast<const float2*>(bias + n);
            float2 v0, v1;
            v0.x = acc[t][j][0] * sc.x + bi.x;
            v0.y = acc[t][j][1] * sc.y + bi.y;
            v1.x = acc[t][j][2] * sc.x + bi.x;
            v1.y = acc[t][j][3] * sc.y + bi.y;
            *reinterpret_cast<float2*>(out + (size_t)r0 * OUT_F + n)       = v0;
            *reinterpret_cast<float2*>(out + (size_t)(r0 + 8) * OUT_F + n) = v1;
        }
    }
}

// ============================================================================
// Host side
// ============================================================================
extern "C" void kernel_launch(void* const* d_in, const int* in_sizes, int n_in,
                              void* d_out, int out_size) {
    const float* x    = (const float*)d_in[0];
    const float* w    = (const float*)d_in[1];
    const float* bias = (const float*)d_in[2];
    float* out = (float*)d_out;

    void *pxh = nullptr, *psgn = nullptr, *pscale = nullptr;
    cudaGetSymbolAddress(&pxh, g_xh);
    cudaGetSymbolAddress(&psgn, g_sgn);
    cudaGetSymbolAddress(&pscale, g_scale);

    // Preprocess (separate launches — fused variant measured slower)
    prep_w_kernel<<<OUT_F, 256>>>(w, (__half*)psgn, (float*)pscale);
    {
        size_t n4 = ((size_t)M_TOTAL * IN_F) / 4;
        prep_x_kernel<<<(unsigned)(n4 / 256), 256>>>(
            (const float4*)x, (__half2*)pxh);
    }

    // Main GEMM
    cudaFuncSetAttribute(hgemm_kernel,
                         cudaFuncAttributeMaxDynamicSharedMemorySize, SMEM_BYTES);

    dim3 grid(OUT_F / BN, M_TOTAL / BM);   // (32, 128)
    hgemm_kernel<<<grid, 256, SMEM_BYTES>>>(bias, out);
}